// round 10
// baseline (speedup 1.0000x reference)
#include <cuda_runtime.h>
#include <cuda_fp16.h>
#include <cstdint>

#define B_SZ    32
#define T_STEPS 200
#define E_DIM   32
#define H_DIM   128
#define V_DIM   8000
#define M_TOT   (B_SZ * T_STEPS)
#define OUT_SEQ_ELEMS ((size_t)M_TOT * V_DIM)

#define MBT     100             // m-tiles: 64 t-major rows = 2 timesteps x 32 batch
#define NB64    125             // n-stripes of 64 (125*64 = 8000 exactly)
#define N_WORK  116             // worker CTAs (32..147)
#define GRID_MAIN 148

// ---------------- globals ----------------------------------------------------
__device__ __align__(128) __half g_hs_h[M_TOT * H_DIM];    // t-major rows
__device__ __align__(128) float  g_ux[B_SZ * T_STEPS * H_DIM];
__device__ int g_cnt[128];      // per-m-tile completion count (==32 when ready)

__global__ void init_kernel() {
    int i = threadIdx.x;
    if (i < 128) g_cnt[i] = 0;
}

// ---------------- packed f32x2 helpers ---------------------------------------
typedef unsigned long long ull;
__device__ __forceinline__ void fma2(ull& d, ull a, ull b) {
    asm("fma.rn.f32x2 %0, %1, %2, %0;" : "+l"(d) : "l"(a), "l"(b));
}
__device__ __forceinline__ ull pk(float x, float y) {
    ull r; asm("mov.b64 %0, {%1,%2};" : "=l"(r) : "f"(x), "f"(y)); return r;
}
__device__ __forceinline__ float2 upk(ull v) {
    float2 r; asm("mov.b64 {%0,%1}, %2;" : "=f"(r.x), "=f"(r.y) : "l"(v)); return r;
}

// ---------------- sync primitives --------------------------------------------
__device__ __forceinline__ int ld_acq(const int* p) {
    int v; asm volatile("ld.acquire.gpu.global.b32 %0, [%1];" : "=r"(v) : "l"(p));
    return v;
}
__device__ __forceinline__ void red_rel_add1(int* p) {
    asm volatile("red.release.gpu.global.add.s32 [%0], 1;" :: "l"(p) : "memory");
}

// ---------------- smem layout -------------------------------------------------
#define LDA2 136
#define TILE_AM (64 * LDA2 * 2)                    // 17408 (A: 64 rows)
#define TILE_B64 (64 * LDA2 * 2 * 2)               // 34816 (B stripe hi+lo)
#define SM_A 0
#define SM_BH(s) (TILE_AM + (s) * TILE_B64)
#define SM_BL(s) (TILE_AM + (s) * TILE_B64 + 64 * LDA2 * 2)
#define DYN_SMEM (TILE_AM + 2 * TILE_B64)          // 87040

#define MMA_FP16(C, A, Bf) asm volatile( \
    "mma.sync.aligned.m16n8k16.row.col.f32.f16.f16.f32 " \
    "{%0,%1,%2,%3}, {%4,%5,%6,%7}, {%8,%9}, {%0,%1,%2,%3};" \
    : "+f"((C)[0]), "+f"((C)[1]), "+f"((C)[2]), "+f"((C)[3]) \
    : "r"((A)[0]), "r"((A)[1]), "r"((A)[2]), "r"((A)[3]), \
      "r"((Bf)[0]), "r"((Bf)[1]))
#define LDSM4(R, P) asm volatile( \
    "ldmatrix.sync.aligned.m8n8.x4.shared.b16 {%0,%1,%2,%3}, [%4];" \
    : "=r"((R)[0]), "=r"((R)[1]), "=r"((R)[2]), "=r"((R)[3]) : "r"(P))
#define LDSM2(R, P) asm volatile( \
    "ldmatrix.sync.aligned.m8n8.x2.shared.b16 {%0,%1}, [%2];" \
    : "=r"((R)[0]), "=r"((R)[1]) : "r"(P))

__device__ __forceinline__ void cpa16(void* dst, const void* src) {
    uint32_t d = (uint32_t)__cvta_generic_to_shared(dst);
    asm volatile("cp.async.cg.shared.global [%0], [%1], 16;"
                 :: "r"(d), "l"(src) : "memory");
}
__device__ __forceinline__ void cpa_commit() {
    asm volatile("cp.async.commit_group;" ::: "memory");
}
__device__ __forceinline__ void cpa_wait_all() {
    asm volatile("cp.async.wait_group 0;" ::: "memory");
}

// A tile: 64 rows x 128 halfs; 256 threads x 4 x 16B
__device__ __forceinline__ void load_A(char* sm, int m, int tid) {
    char* As = sm + SM_A;
    #pragma unroll
    for (int it = 0; it < 4; it++) {
        int id  = it * 256 + tid;
        int row = id >> 4;
        int c   = (id & 15) * 8;
        cpa16(As + row * (LDA2 * 2) + c * 2,
              &g_hs_h[(size_t)(m * 64 + row) * H_DIM + c]);
    }
}

// B stripe: 64 Vw rows, fp32 -> fp16 hi + lo residual, direct to smem (once)
__device__ __forceinline__ void load_B64(char* sm, int slot, int nb,
                                         const float* __restrict__ Vw, int tid) {
    __half* Bh = (__half*)(sm + SM_BH(slot));
    __half* Bl = (__half*)(sm + SM_BL(slot));
    const int row = tid >> 2;               // 64 rows, 4 threads/row
    const int c0  = (tid & 3) * 32;         // 32 cols per thread
    const float* src = Vw + (size_t)(nb * 64 + row) * H_DIM + c0;
    #pragma unroll
    for (int i = 0; i < 8; i++) {
        float4 v = *(const float4*)(src + 4 * i);
        __half h0 = __float2half(v.x), h1 = __float2half(v.y);
        __half h2 = __float2half(v.z), h3 = __float2half(v.w);
        __half l0 = __float2half(v.x - __half2float(h0));
        __half l1 = __float2half(v.y - __half2float(h1));
        __half l2 = __float2half(v.z - __half2float(h2));
        __half l3 = __float2half(v.w - __half2float(h3));
        __half2* dh = (__half2*)(Bh + row * LDA2 + c0 + 4 * i);
        __half2* dl = (__half2*)(Bl + row * LDA2 + c0 + 4 * i);
        dh[0] = __halves2half2(h0, h1); dh[1] = __halves2half2(h2, h3);
        dl[0] = __halves2half2(l0, l1); dl[1] = __halves2half2(l2, l3);
    }
}

// one 64(M) x 64(N) tile: 8 warps as 2(M)x4(N) of 32x16; 2-pass fp16
__device__ __forceinline__ void compute_tile64(char* sm, int slot, int m, int nb,
                                               const float* __restrict__ Vb,
                                               float* __restrict__ out, int tid) {
    const int w    = tid >> 5;
    const int lane = tid & 31;
    const int wm = (w >> 2) * 32;   // 0,32
    const int wn = (w & 3) * 16;    // 0,16,32,48
    const int a_rl = lane & 15;
    const int a_co = (lane >> 4) * 8;
    const int b_rl = lane & 7;
    const int b_co = lane & 8;
    char* Ahs = sm + SM_A;
    char* Bhs = sm + SM_BH(slot);
    char* Bls = sm + SM_BL(slot);

    float acc[2][2][4];
    #pragma unroll
    for (int i = 0; i < 2; i++)
        #pragma unroll
        for (int jj = 0; jj < 2; jj++)
            #pragma unroll
            for (int k = 0; k < 4; k++) acc[i][jj][k] = 0.0f;

    #pragma unroll
    for (int kc = 0; kc < 8; kc++) {
        const int kb = kc * 16;
        unsigned ah[2][4], bh[2][2], bl[2][2];
        #pragma unroll
        for (int rb = 0; rb < 2; rb++) {
            unsigned p = (unsigned)__cvta_generic_to_shared(
                Ahs + (wm + rb * 16 + a_rl) * (LDA2 * 2) + (kb + a_co) * 2);
            LDSM4(ah[rb], p);
        }
        #pragma unroll
        for (int cb = 0; cb < 2; cb++) {
            unsigned p = (unsigned)__cvta_generic_to_shared(
                Bhs + (wn + cb * 8 + b_rl) * (LDA2 * 2) + (kb + b_co) * 2);
            LDSM2(bh[cb], p);
            p = (unsigned)__cvta_generic_to_shared(
                Bls + (wn + cb * 8 + b_rl) * (LDA2 * 2) + (kb + b_co) * 2);
            LDSM2(bl[cb], p);
        }
        #pragma unroll
        for (int rb = 0; rb < 2; rb++)
            #pragma unroll
            for (int cb = 0; cb < 2; cb++)
                MMA_FP16(acc[rb][cb], ah[rb], bh[cb]);
        #pragma unroll
        for (int rb = 0; rb < 2; rb++)
            #pragma unroll
            for (int cb = 0; cb < 2; cb++)
                MMA_FP16(acc[rb][cb], ah[rb], bl[cb]);
    }

    // epilogue: smem rows are t-major (r = t*32 + b) -> out row = b*200 + t
    #pragma unroll
    for (int rb = 0; rb < 2; rb++) {
        int r0 = m * 64 + wm + rb * 16 + (lane >> 2);
        int or0 = (r0 & 31) * T_STEPS + (r0 >> 5);
        int r1 = r0 + 8;
        int or1 = (r1 & 31) * T_STEPS + (r1 >> 5);
        #pragma unroll
        for (int cb = 0; cb < 2; cb++) {
            int col = nb * 64 + wn + cb * 8 + (lane & 3) * 2;
            float2 bv = *(const float2*)&Vb[col];
            float2 o0, o1;
            o0.x = acc[rb][cb][0] + bv.x; o0.y = acc[rb][cb][1] + bv.y;
            o1.x = acc[rb][cb][2] + bv.x; o1.y = acc[rb][cb][3] + bv.y;
            *(float2*)&out[(size_t)or0 * V_DIM + col] = o0;
            *(float2*)&out[(size_t)or1 * V_DIM + col] = o1;
        }
    }
}

// ---------------- fused persistent kernel ------------------------------------
__global__ void __launch_bounds__(256) fused_kernel(
    const float* __restrict__ x,  const float* __restrict__ Ww,
    const float* __restrict__ Wb, const float* __restrict__ Uw,
    const float* __restrict__ Ub, const float* __restrict__ Vw,
    const float* __restrict__ Vb, float* __restrict__ out,
    float* __restrict__ hidden_out)
{
    extern __shared__ __align__(16) char dynsm[];
    const int tid = threadIdx.x;
    const int cta = blockIdx.x;

    if (cta < B_SZ) {
        // ================= RECURRENCE (producer) =================
        float* xs = (float*)dynsm;                  // 200*32 floats
        float* hb = xs + T_STEPS * E_DIM;           // 2*136 floats
        const int b = cta;

        const float* xb = x + (size_t)b * T_STEPS * E_DIM;
        for (int i = tid; i < T_STEPS * E_DIM; i += 256) xs[i] = xb[i];
        if (tid < 136) { hb[tid] = 0.0f; hb[136 + tid] = 0.0f; }
        __syncthreads();

        // phase 1: ux -> global scratch
        {
            const int jj = tid & 127;
            const int g  = tid >> 7;
            ull up[16];
            const float2* ur = (const float2*)(Uw + jj * E_DIM);
            #pragma unroll
            for (int i = 0; i < 16; i++) { float2 v = ur[i]; up[i] = pk(v.x, v.y); }
            const float biasj = Wb[jj] + Ub[jj];
            float* uxb = g_ux + (size_t)b * T_STEPS * H_DIM;
            for (int t = g * 100; t < g * 100 + 100; t++) {
                ull a[4];
                a[0] = pk(0.f, 0.f); a[1] = a[0]; a[2] = a[0]; a[3] = a[0];
                const ulonglong2* xt = (const ulonglong2*)(xs + t * E_DIM);
                #pragma unroll
                for (int i = 0; i < 8; i++) {
                    ulonglong2 v = xt[i];
                    fma2(a[(2 * i) & 3],     up[2 * i],     v.x);
                    fma2(a[(2 * i + 1) & 3], up[2 * i + 1], v.y);
                }
                float2 s0 = upk(a[0]), s1 = upk(a[1]), s2 = upk(a[2]), s3 = upk(a[3]);
                uxb[t * H_DIM + jj] = ((s0.x + s0.y) + (s1.x + s1.y))
                                    + ((s2.x + s2.y) + (s3.x + s3.y)) + biasj;
            }
        }

        // phase 2: recurrence; tid = j*2 + q
        const int j = tid >> 1;
        const int q = tid & 1;
        ull wp[32];
        {
            const float4* wr = (const float4*)(Ww + j * H_DIM + q * 64);
            #pragma unroll
            for (int i = 0; i < 16; i++) {
                float4 v = wr[i];
                wp[2 * i]     = pk(v.x, v.y);
                wp[2 * i + 1] = pk(v.z, v.w);
            }
        }
        __syncthreads();

        const int hrd = q * 68;
        const int wch = (j >> 6) * 68 + (j & 63);
        const float* uxb = g_ux + (size_t)b * T_STEPS * H_DIM;
        float ucur = (q == 0) ? uxb[j] : 0.0f;

        for (int t = 0; t < T_STEPS; t++) {
            float unext = 0.0f;
            if (q == 0 && t + 1 < T_STEPS) unext = uxb[(t + 1) * H_DIM + j];

            const ulonglong2* hr = (const ulonglong2*)(hb + (t & 1) * 136 + hrd);
            ull a[4];
            a[0] = pk(0.f, 0.f); a[1] = a[0]; a[2] = a[0]; a[3] = a[0];
            #pragma unroll
            for (int i = 0; i < 16; i++) {
                ulonglong2 v = hr[i];
                fma2(a[(2 * i) & 3],     wp[2 * i],     v.x);
                fma2(a[(2 * i + 1) & 3], wp[2 * i + 1], v.y);
            }
            float2 s0 = upk(a[0]), s1 = upk(a[1]), s2 = upk(a[2]), s3 = upk(a[3]);
            float acc = ((s0.x + s0.y) + (s1.x + s1.y))
                      + ((s2.x + s2.y) + (s3.x + s3.y));
            acc += __shfl_xor_sync(0xffffffffu, acc, 1);

            if (q == 0) {
                acc += ucur;
                float e;
                asm("ex2.approx.f32 %0, %1;" : "=f"(e)
                    : "f"(acc * 2.8853900817779268f));
                float r;
                asm("rcp.approx.f32 %0, %1;" : "=f"(r) : "f"(e + 1.0f));
                float hv = fmaf(-2.0f, r, 1.0f);
                hb[((t + 1) & 1) * 136 + wch] = hv;
                g_hs_h[((size_t)t * B_SZ + b) * H_DIM + j] = __float2half(hv);
                if (t == T_STEPS - 1) hidden_out[b * H_DIM + j] = hv;
            }
            ucur = unext;
            if (t & 1) __threadfence();
            __syncthreads();
            if ((t & 1) && tid == 0) red_rel_add1(&g_cnt[t >> 1]);
        }
        return;
    }

    // ================= GEMM worker: fixed n-stripe(s), resident B ============
    const int widx = cta - B_SZ;                 // 0..115
    const int nb0 = widx;
    const int nb1 = widx + N_WORK;               // 116..231; valid if < 125
    const int nbl = (nb1 < NB64) ? 2 : 1;

    load_B64(dynsm, 0, nb0, Vw, tid);            // once: fp32->hi/lo fp16
    if (nbl == 2) load_B64(dynsm, 1, nb1, Vw, tid);
    __syncthreads();

    for (int m = 0; m < MBT; m++) {
        if (tid == 0) {
            while (ld_acq(&g_cnt[m]) < B_SZ) __nanosleep(64);
        }
        __syncthreads();
        load_A(dynsm, m, tid);
        cpa_commit();
        cpa_wait_all();
        __syncthreads();

        compute_tile64(dynsm, 0, m, nb0, Vb, out, tid);
        if (nbl == 2) compute_tile64(dynsm, 1, m, nb1, Vb, out, tid);
        __syncthreads();                          // A reads done before next m
    }
}

// ---------------- launch ----------------------------------------------------
extern "C" void kernel_launch(void* const* d_in, const int* in_sizes, int n_in,
                              void* d_out, int out_size) {
    const float* x  = (const float*)d_in[0];
    const float* Ww = (const float*)d_in[1];
    const float* Wb = (const float*)d_in[2];
    const float* Uw = (const float*)d_in[3];
    const float* Ub = (const float*)d_in[4];
    const float* Vw = (const float*)d_in[5];
    const float* Vb = (const float*)d_in[6];
    float* out = (float*)d_out;

    cudaFuncSetAttribute(fused_kernel,
                         cudaFuncAttributeMaxDynamicSharedMemorySize, DYN_SMEM);

    init_kernel<<<1, 128>>>();
    fused_kernel<<<GRID_MAIN, 256, DYN_SMEM>>>(x, Ww, Wb, Uw, Ub, Vw, Vb, out,
                                               out + OUT_SEQ_ELEMS);
}

// round 11
// speedup vs baseline: 1.8284x; 1.8284x over previous
#include <cuda_runtime.h>
#include <cuda_fp16.h>
#include <cstdint>

#define B_SZ    32
#define T_STEPS 200
#define E_DIM   32
#define H_DIM   128
#define V_DIM   8000
#define M_TOT   (B_SZ * T_STEPS)
#define OUT_SEQ_ELEMS ((size_t)M_TOT * V_DIM)

#define MBT     100             // m-tiles: 64 t-major rows = 2 timesteps x 32 batch
#define NB64    125             // n-stripes of 64
#define N_WORK  116             // worker CTAs own stripes 0..115
#define NB_XTRA 9               // stripes 116..124 -> chunk pool
#define MBLK    10              // m per chunk
#define NCHUNK  (NB_XTRA * (MBT / MBLK))   // 90
#define GRID_MAIN 148
#define STR 32                  // g_cnt stride in ints (128B)

// ---------------- globals ----------------------------------------------------
__device__ __align__(128) __half g_hs_h[M_TOT * H_DIM];    // t-major rows
__device__ int g_cnt[20 * STR]; // per-10-step batch completion (==32 ready)
__device__ int g_chunk;

__global__ void init_kernel() {
    for (int i = threadIdx.x; i < 20 * STR; i += blockDim.x) g_cnt[i] = 0;
    if (threadIdx.x == 0) g_chunk = 0;
}

// ---------------- packed f32x2 helpers ---------------------------------------
typedef unsigned long long ull;
__device__ __forceinline__ void fma2(ull& d, ull a, ull b) {
    asm("fma.rn.f32x2 %0, %1, %2, %0;" : "+l"(d) : "l"(a), "l"(b));
}
__device__ __forceinline__ ull pk(float x, float y) {
    ull r; asm("mov.b64 %0, {%1,%2};" : "=l"(r) : "f"(x), "f"(y)); return r;
}
__device__ __forceinline__ float2 upk(ull v) {
    float2 r; asm("mov.b64 {%0,%1}, %2;" : "=f"(r.x), "=f"(r.y) : "l"(v)); return r;
}

// ---------------- sync primitives --------------------------------------------
__device__ __forceinline__ int ld_acq(const int* p) {
    int v; asm volatile("ld.acquire.gpu.global.b32 %0, [%1];" : "=r"(v) : "l"(p));
    return v;
}
__device__ __forceinline__ void red_rel_add1(int* p) {
    asm volatile("red.release.gpu.global.add.s32 [%0], 1;" :: "l"(p) : "memory");
}

// ---------------- smem layout -------------------------------------------------
// rec:    ux[200*128]f32 (102400) | xs[200*32] (25600) | hb[2*136] (1088) = 129088
// worker: A0 (17408) | A1 (17408) | Bh (17408) | Bl (17408) = 69632
#define LDA2 136
#define TILE_AM (64 * LDA2 * 2)                    // 17408
#define SM_BW   (2 * TILE_AM)
#define DYN_SMEM 129088

#define MMA_FP16(C, A, Bf) asm volatile( \
    "mma.sync.aligned.m16n8k16.row.col.f32.f16.f16.f32 " \
    "{%0,%1,%2,%3}, {%4,%5,%6,%7}, {%8,%9}, {%0,%1,%2,%3};" \
    : "+f"((C)[0]), "+f"((C)[1]), "+f"((C)[2]), "+f"((C)[3]) \
    : "r"((A)[0]), "r"((A)[1]), "r"((A)[2]), "r"((A)[3]), \
      "r"((Bf)[0]), "r"((Bf)[1]))
#define LDSM4(R, P) asm volatile( \
    "ldmatrix.sync.aligned.m8n8.x4.shared.b16 {%0,%1,%2,%3}, [%4];" \
    : "=r"((R)[0]), "=r"((R)[1]), "=r"((R)[2]), "=r"((R)[3]) : "r"(P))
#define LDSM2(R, P) asm volatile( \
    "ldmatrix.sync.aligned.m8n8.x2.shared.b16 {%0,%1}, [%2];" \
    : "=r"((R)[0]), "=r"((R)[1]) : "r"(P))

__device__ __forceinline__ void cpa16(void* dst, const void* src) {
    uint32_t d = (uint32_t)__cvta_generic_to_shared(dst);
    asm volatile("cp.async.cg.shared.global [%0], [%1], 16;"
                 :: "r"(d), "l"(src) : "memory");
}
__device__ __forceinline__ void cpa_commit() {
    asm volatile("cp.async.commit_group;" ::: "memory");
}
__device__ __forceinline__ void cpa_wait_all() {
    asm volatile("cp.async.wait_group 0;" ::: "memory");
}

// A tile: 64 rows x 128 halfs; 256 threads x 4 x 16B
__device__ __forceinline__ void load_A(char* As, int m, int tid) {
    #pragma unroll
    for (int it = 0; it < 4; it++) {
        int id  = it * 256 + tid;
        int row = id >> 4;
        int c   = (id & 15) * 8;
        cpa16(As + row * (LDA2 * 2) + c * 2,
              &g_hs_h[(size_t)(m * 64 + row) * H_DIM + c]);
    }
}

// B stripe: 64 Vw rows, fp32 -> fp16 hi + lo residual (direct to smem)
__device__ __forceinline__ void load_B64(char* bbase, int nb,
                                         const float* __restrict__ Vw, int tid) {
    __half* Bh = (__half*)bbase;
    __half* Bl = (__half*)(bbase + TILE_AM);
    const int row = tid >> 2;
    const int c0  = (tid & 3) * 32;
    const float* src = Vw + (size_t)(nb * 64 + row) * H_DIM + c0;
    #pragma unroll
    for (int i = 0; i < 8; i++) {
        float4 v = *(const float4*)(src + 4 * i);
        __half h0 = __float2half(v.x), h1 = __float2half(v.y);
        __half h2 = __float2half(v.z), h3 = __float2half(v.w);
        __half l0 = __float2half(v.x - __half2float(h0));
        __half l1 = __float2half(v.y - __half2float(h1));
        __half l2 = __float2half(v.z - __half2float(h2));
        __half l3 = __float2half(v.w - __half2float(h3));
        __half2* dh = (__half2*)(Bh + row * LDA2 + c0 + 4 * i);
        __half2* dl = (__half2*)(Bl + row * LDA2 + c0 + 4 * i);
        dh[0] = __halves2half2(h0, h1); dh[1] = __halves2half2(h2, h3);
        dl[0] = __halves2half2(l0, l1); dl[1] = __halves2half2(l2, l3);
    }
}

// one 64(M) x 64(N) tile: 8 warps as 2(M)x4(N); 2-pass fp16
__device__ __forceinline__ void compute_tile64(const char* Ahs, const char* bbase,
                                               int m, int nb,
                                               const float* __restrict__ Vb,
                                               float* __restrict__ out, int tid) {
    const int w    = tid >> 5;
    const int lane = tid & 31;
    const int wm = (w >> 2) * 32;
    const int wn = (w & 3) * 16;
    const int a_rl = lane & 15;
    const int a_co = (lane >> 4) * 8;
    const int b_rl = lane & 7;
    const int b_co = lane & 8;
    const char* Bhs = bbase;
    const char* Bls = bbase + TILE_AM;

    float acc[2][2][4];
    #pragma unroll
    for (int i = 0; i < 2; i++)
        #pragma unroll
        for (int jj = 0; jj < 2; jj++)
            #pragma unroll
            for (int k = 0; k < 4; k++) acc[i][jj][k] = 0.0f;

    #pragma unroll
    for (int kc = 0; kc < 8; kc++) {
        const int kb = kc * 16;
        unsigned ah[2][4], bh[2][2], bl[2][2];
        #pragma unroll
        for (int rb = 0; rb < 2; rb++) {
            unsigned p = (unsigned)__cvta_generic_to_shared(
                Ahs + (wm + rb * 16 + a_rl) * (LDA2 * 2) + (kb + a_co) * 2);
            LDSM4(ah[rb], p);
        }
        #pragma unroll
        for (int cb = 0; cb < 2; cb++) {
            unsigned p = (unsigned)__cvta_generic_to_shared(
                Bhs + (wn + cb * 8 + b_rl) * (LDA2 * 2) + (kb + b_co) * 2);
            LDSM2(bh[cb], p);
            p = (unsigned)__cvta_generic_to_shared(
                Bls + (wn + cb * 8 + b_rl) * (LDA2 * 2) + (kb + b_co) * 2);
            LDSM2(bl[cb], p);
        }
        #pragma unroll
        for (int rb = 0; rb < 2; rb++)
            #pragma unroll
            for (int cb = 0; cb < 2; cb++)
                MMA_FP16(acc[rb][cb], ah[rb], bh[cb]);
        #pragma unroll
        for (int rb = 0; rb < 2; rb++)
            #pragma unroll
            for (int cb = 0; cb < 2; cb++)
                MMA_FP16(acc[rb][cb], ah[rb], bl[cb]);
    }

    // rows t-major (r = t*32+b) -> out row = b*200 + t
    #pragma unroll
    for (int rb = 0; rb < 2; rb++) {
        int r0 = m * 64 + wm + rb * 16 + (lane >> 2);
        int or0 = (r0 & 31) * T_STEPS + (r0 >> 5);
        int r1 = r0 + 8;
        int or1 = (r1 & 31) * T_STEPS + (r1 >> 5);
        #pragma unroll
        for (int cb = 0; cb < 2; cb++) {
            int col = nb * 64 + wn + cb * 8 + (lane & 3) * 2;
            float2 bv = *(const float2*)&Vb[col];
            float2 o0, o1;
            o0.x = acc[rb][cb][0] + bv.x; o0.y = acc[rb][cb][1] + bv.y;
            o1.x = acc[rb][cb][2] + bv.x; o1.y = acc[rb][cb][3] + bv.y;
            *(float2*)&out[(size_t)or0 * V_DIM + col] = o0;
            *(float2*)&out[(size_t)or1 * V_DIM + col] = o1;
        }
    }
}

// ---------------- leftover chunk pool (stripes 116..124) ----------------------
__device__ void chunk_pool(char* sm, const float* __restrict__ Vw,
                           const float* __restrict__ Vb, float* __restrict__ out,
                           int tid, volatile int* s_flag) {
    int bres = -1;
    for (;;) {
        if (tid == 0) *s_flag = atomicAdd(&g_chunk, 1);
        __syncthreads();
        int c = *s_flag;
        __syncthreads();
        if (c >= NCHUNK) return;
        const int nb = N_WORK + c / (MBT / MBLK);
        const int mb = c % (MBT / MBLK);
        if (bres != nb) { load_B64(sm + SM_BW, nb, Vw, tid); bres = nb; }
        if (tid == 0) {
            while (ld_acq(&g_cnt[(2 * mb + 1) * STR]) < B_SZ) __nanosleep(256);
        }
        __syncthreads();                           // B conversion + readiness
        const int m0 = mb * MBLK;
        load_A(sm, m0, tid);
        cpa_commit(); cpa_wait_all(); __syncthreads();
        int cur = 0;
        for (int k = 0; k < MBLK; k++) {
            bool nxt = (k + 1 < MBLK);
            if (nxt) { load_A(sm + (cur ^ 1) * TILE_AM, m0 + k + 1, tid); cpa_commit(); }
            compute_tile64(sm + cur * TILE_AM, sm + SM_BW, m0 + k, nb, Vb, out, tid);
            if (nxt) cpa_wait_all();
            __syncthreads();
            cur ^= 1;
        }
    }
}

// ---------------- fused persistent kernel ------------------------------------
__global__ void __launch_bounds__(256) fused_kernel(
    const float* __restrict__ x,  const float* __restrict__ Ww,
    const float* __restrict__ Wb, const float* __restrict__ Uw,
    const float* __restrict__ Ub, const float* __restrict__ Vw,
    const float* __restrict__ Vb, float* __restrict__ out,
    float* __restrict__ hidden_out)
{
    extern __shared__ __align__(16) char dynsm[];
    __shared__ int s_flag;
    const int tid = threadIdx.x;
    const int cta = blockIdx.x;

    if (cta < B_SZ) {
        // ================= RECURRENCE (producer; R8 numerics) =================
        float* ux = (float*)dynsm;                   // 200*128
        float* xs = ux + T_STEPS * H_DIM;            // 200*32
        float* hb = xs + T_STEPS * E_DIM;            // 2*136
        const int b = cta;

        const float* xb = x + (size_t)b * T_STEPS * E_DIM;
        for (int i = tid; i < T_STEPS * E_DIM; i += 256) xs[i] = xb[i];
        if (tid < 136) { hb[tid] = 0.0f; hb[136 + tid] = 0.0f; }
        __syncthreads();

        // phase 1: ux in smem
        {
            const int jj = tid & 127;
            const int g  = tid >> 7;
            ull up[16];
            const float2* ur = (const float2*)(Uw + jj * E_DIM);
            #pragma unroll
            for (int i = 0; i < 16; i++) { float2 v = ur[i]; up[i] = pk(v.x, v.y); }
            const float biasj = Wb[jj] + Ub[jj];
            for (int t = g * 100; t < g * 100 + 100; t++) {
                ull a[4];
                a[0] = pk(0.f, 0.f); a[1] = a[0]; a[2] = a[0]; a[3] = a[0];
                const ulonglong2* xt = (const ulonglong2*)(xs + t * E_DIM);
                #pragma unroll
                for (int i = 0; i < 8; i++) {
                    ulonglong2 v = xt[i];
                    fma2(a[(2 * i) & 3],     up[2 * i],     v.x);
                    fma2(a[(2 * i + 1) & 3], up[2 * i + 1], v.y);
                }
                float2 s0 = upk(a[0]), s1 = upk(a[1]), s2 = upk(a[2]), s3 = upk(a[3]);
                ux[t * H_DIM + jj] = ((s0.x + s0.y) + (s1.x + s1.y))
                                   + ((s2.x + s2.y) + (s3.x + s3.y)) + biasj;
            }
        }

        // phase 2: recurrence; tid = j*2 + q
        const int j = tid >> 1;
        const int q = tid & 1;
        ull wp[32];
        {
            const float4* wr = (const float4*)(Ww + j * H_DIM + q * 64);
            #pragma unroll
            for (int i = 0; i < 16; i++) {
                float4 v = wr[i];
                wp[2 * i]     = pk(v.x, v.y);
                wp[2 * i + 1] = pk(v.z, v.w);
            }
        }
        __syncthreads();

        const int hrd = q * 68;
        const int wch = (j >> 6) * 68 + (j & 63);

        for (int t = 0; t < T_STEPS; t++) {
            const ulonglong2* hr = (const ulonglong2*)(hb + (t & 1) * 136 + hrd);
            ull a[4];
            a[0] = pk(0.f, 0.f); a[1] = a[0]; a[2] = a[0]; a[3] = a[0];
            #pragma unroll
            for (int i = 0; i < 16; i++) {
                ulonglong2 v = hr[i];
                fma2(a[(2 * i) & 3],     wp[2 * i],     v.x);
                fma2(a[(2 * i + 1) & 3], wp[2 * i + 1], v.y);
            }
            float2 s0 = upk(a[0]), s1 = upk(a[1]), s2 = upk(a[2]), s3 = upk(a[3]);
            float acc = ((s0.x + s0.y) + (s1.x + s1.y))
                      + ((s2.x + s2.y) + (s3.x + s3.y));
            acc += __shfl_xor_sync(0xffffffffu, acc, 1);
            acc += ux[t * H_DIM + j];

            float e;
            asm("ex2.approx.f32 %0, %1;" : "=f"(e)
                : "f"(acc * 2.8853900817779268f));
            float r;
            asm("rcp.approx.f32 %0, %1;" : "=f"(r) : "f"(e + 1.0f));
            float hv = fmaf(-2.0f, r, 1.0f);

            if (q == 0) {
                hb[((t + 1) & 1) * 136 + wch] = hv;
                g_hs_h[((size_t)t * B_SZ + b) * H_DIM + j] = __float2half(hv);
                if (t == T_STEPS - 1) hidden_out[b * H_DIM + j] = hv;
            }
            if ((t % 10) == 9) __threadfence();      // 20 fences total
            __syncthreads();
            if ((t % 10) == 9 && tid == 0)
                red_rel_add1(&g_cnt[(t / 10) * STR]);
        }
        __syncthreads();
        chunk_pool(dynsm, Vw, Vb, out, tid, &s_flag);
        return;
    }

    // ================= GEMM worker: fixed stripe, resident B =================
    const int nb = cta - B_SZ;                       // 0..115
    load_B64(dynsm + SM_BW, nb, Vw, tid);            // once
    __syncthreads();

    int cur = 0;
    bool havA = false;
    for (int m = 0; m < MBT; m++) {
        if (!havA) {
            if (tid == 0) {
                while (ld_acq(&g_cnt[(m / 5) * STR]) < B_SZ) __nanosleep(256);
            }
            __syncthreads();
            load_A(dynsm + cur * TILE_AM, m, tid);
            cpa_commit(); cpa_wait_all(); __syncthreads();
        }
        bool nxt;
        if (m + 1 >= MBT) nxt = false;
        else if ((m + 1) / 5 == m / 5) nxt = true;
        else {
            if (tid == 0) s_flag = (ld_acq(&g_cnt[((m + 1) / 5) * STR]) >= B_SZ);
            __syncthreads();
            nxt = (s_flag != 0);
        }
        if (nxt) { load_A(dynsm + (cur ^ 1) * TILE_AM, m + 1, tid); cpa_commit(); }

        compute_tile64(dynsm + cur * TILE_AM, dynsm + SM_BW, m, nb, Vb, out, tid);

        if (nxt) cpa_wait_all();
        __syncthreads();
        if (nxt) { cur ^= 1; havA = true; } else havA = false;
    }
    chunk_pool(dynsm, Vw, Vb, out, tid, &s_flag);
}

// ---------------- launch ----------------------------------------------------
extern "C" void kernel_launch(void* const* d_in, const int* in_sizes, int n_in,
                              void* d_out, int out_size) {
    const float* x  = (const float*)d_in[0];
    const float* Ww = (const float*)d_in[1];
    const float* Wb = (const float*)d_in[2];
    const float* Uw = (const float*)d_in[3];
    const float* Ub = (const float*)d_in[4];
    const float* Vw = (const float*)d_in[5];
    const float* Vb = (const float*)d_in[6];
    float* out = (float*)d_out;

    cudaFuncSetAttribute(fused_kernel,
                         cudaFuncAttributeMaxDynamicSharedMemorySize, DYN_SMEM);

    init_kernel<<<1, 256>>>();
    fused_kernel<<<GRID_MAIN, 256, DYN_SMEM>>>(x, Ww, Wb, Uw, Ub, Vw, Vb, out,
                                               out + OUT_SEQ_ELEMS);
}